// round 16
// baseline (speedup 1.0000x reference)
#include <cuda_runtime.h>
#include <cuda_fp16.h>
#include <cstdint>
#include <math.h>

// ============================================================================
//   M = Wq @ Wk^T (768x768).   c = Wq @ (noise@Wk).
//   P = X @ [M | Wv | W1a | W1b] : [65536, 1920]  (m | v | h_a | h_b)
//   d_self = (m + c).x ;  d_cross = m.x_other
// ============================================================================
#define MTOT   65536
#define HALFM  32768
#define DIM    768
#define NPAD   1920
#define KPA    768
#define KPB    768
#define KEFF   768

#define BM 128
#define BN 128
#define BK 64
#define KT (KEFF / BK)         // 12
#define STAGES 3
#define STAGE_BYTES 32768      // A 16KB + B 16KB
#define SM_TOTAL (STAGES * STAGE_BYTES)   // 96 KB -> 2 CTAs/SM

// ============================================================================
// Scratch
// ============================================================================
__device__ __half g_Xc  [(long)MTOT * KPA];
__device__ __half g_Wc  [(long)NPAD * KPB];
__device__ __half g_P   [(long)MTOT * NPAD];
__device__ __half g_Wq16[(long)DIM * DIM];
__device__ __half g_Wk16[(long)DIM * DIM];
__device__ float  g_nk[DIM];
__device__ float  g_c [DIM];

// ============================================================================
// Helpers
// ============================================================================
__device__ __forceinline__ uint32_t smem_to_u32(const void* smem_ptr) {
    uint32_t addr;
    asm("{ .reg .u64 tmp; cvta.to.shared.u64 tmp, %1; cvt.u32.u64 %0, tmp; }"
        : "=r"(addr) : "l"(smem_ptr));
    return addr;
}

#define SWZ(byte_offset) ((byte_offset) ^ ((((uint32_t)(byte_offset)) >> 3) & 0x70))

__device__ __forceinline__ void cp_async16(uint32_t dst_smem, const void* src) {
    asm volatile("cp.async.cg.shared.global [%0], [%1], 16;"
        :: "r"(dst_smem), "l"(src) : "memory");
}
#define CP_ASYNC_COMMIT()  asm volatile("cp.async.commit_group;" ::: "memory")
#define CP_ASYNC_WAIT(N)   asm volatile("cp.async.wait_group %0;" :: "n"(N) : "memory")

__device__ __forceinline__ void ldsm_x4(uint32_t* r, uint32_t addr) {
    asm volatile("ldmatrix.sync.aligned.m8n8.x4.shared.b16 {%0,%1,%2,%3}, [%4];"
        : "=r"(r[0]), "=r"(r[1]), "=r"(r[2]), "=r"(r[3]) : "r"(addr));
}

__device__ __forceinline__ void mma16816(float* c, const uint32_t* a, const uint32_t* b) {
    asm volatile(
        "mma.sync.aligned.m16n8k16.row.col.f32.f16.f16.f32 "
        "{%0,%1,%2,%3}, {%4,%5,%6,%7}, {%8,%9}, {%0,%1,%2,%3};"
        : "+f"(c[0]), "+f"(c[1]), "+f"(c[2]), "+f"(c[3])
        : "r"(a[0]), "r"(a[1]), "r"(a[2]), "r"(a[3]), "r"(b[0]), "r"(b[1]));
}

// ============================================================================
// Prep kernels
// ============================================================================
#define N4H   ((long)HALFM * DIM / 4)        // float4 count per input (6291456)
#define XBLK4 ((unsigned)(2 * N4H / 1024))   // 12288 blocks, 4 float4/thread

// One kernel: [0,768) qk rows | [768,1920) w rows | [1920,..) x chunks (MLP=4)
__global__ void prep_all_kernel(const float*  __restrict__ Wq,
                                const float*  __restrict__ Wk,
                                const float*  __restrict__ Wv,
                                const float*  __restrict__ W1,
                                const float4* __restrict__ x1,
                                const float4* __restrict__ x2) {
    const int b = blockIdx.x;
    if (b < 768) {
        long i = b;
        for (int e = threadIdx.x; e < DIM; e += blockDim.x) {
            g_Wq16[i * DIM + e] = __float2half(Wq[i * DIM + e]);
            g_Wk16[i * DIM + e] = __float2half(Wk[i * DIM + e]);
        }
    } else if (b < 1920) {
        int n = b;  // 768..1919
        __half* dst = g_Wc + (long)n * KPB;
        for (int j = threadIdx.x; j < DIM; j += blockDim.x) {
            float w;
            if      (n < 1536) w = Wv[j * 768 + (n - 768)];
            else if (n < 1728) w = W1[j * 192 + (n - 1536)];
            else               w = W1[(768 + j) * 192 + (n - 1728)];
            dst[j] = __float2half(w);
        }
    } else {
        // 4 independent float4 conversions per thread (MLP=4)
        const long base = (long)(b - 1920) * 1024 + threadIdx.x;
        float4 v[4];
        #pragma unroll
        for (int u = 0; u < 4; u++) {
            long i = base + u * 256;
            v[u] = (i < N4H) ? x1[i] : x2[i - N4H];
        }
        #pragma unroll
        for (int u = 0; u < 4; u++) {
            long i = base + u * 256;
            __half2 lo = __floats2half2_rn(v[u].x, v[u].y);
            __half2 hi = __floats2half2_rn(v[u].z, v[u].w);
            uint2 pack;
            pack.x = *(uint32_t*)&lo;
            pack.y = *(uint32_t*)&hi;
            ((uint2*)g_Xc)[i] = pack;
        }
    }
}

__global__ void zero_nk_kernel() {
    if (threadIdx.x < DIM) g_nk[threadIdx.x] = 0.0f;
}

__global__ void nk_partial_kernel(const float* __restrict__ noise,
                                  const float* __restrict__ Wk) {
    const int d  = blockIdx.x * 128 + threadIdx.x;
    const int j0 = blockIdx.y * 48;
    float acc = 0.0f;
    #pragma unroll
    for (int j = 0; j < 48; j++)
        acc += noise[j0 + j] * Wk[(long)(j0 + j) * 768 + d];
    atomicAdd(&g_nk[d], acc);
}

__global__ void c_kernel(const float* __restrict__ Wq) {
    const int wid  = threadIdx.x >> 5;
    const int lane = threadIdx.x & 31;
    const int d    = blockIdx.x * 8 + wid;
    float acc = 0.0f;
    #pragma unroll
    for (int i = 0; i < 24; i++) {
        int e = lane + i * 32;
        acc += Wq[(long)d * 768 + e] * g_nk[e];
    }
    #pragma unroll
    for (int o = 16; o; o >>= 1) acc += __shfl_xor_sync(0xFFFFFFFFu, acc, o);
    if (lane == 0) g_c[d] = acc;
}

// ============================================================================
// Persistent fp16 GEMM: C[m][n] = sum_k A[m][k]*B[n][k], K=768.
// BM=BN=128, BK=64. 128 threads, 4 warps (2m x 2n), 64x64 warp tiles,
// 3-stage cp.async, 96 KB smem, 2 CTAs/SM.
// Grid-stride over tiles: no wave transitions; next tile's first two stage
// loads are issued BEFORE the epilogue (stages 0/1 proven idle there).
// ============================================================================
__global__ void __launch_bounds__(128, 2)
hgemm_kernel(const __half* __restrict__ A, const __half* __restrict__ B,
             __half* __restrict__ C, int ldc, int ntiles, int nbx) {
    extern __shared__ char smem[];
    const uint32_t sbase = smem_to_u32(smem);
    const int tid    = threadIdx.x;
    const int wid    = tid >> 5;
    const int lane   = tid & 31;
    const int warp_m = wid >> 1;  // 0..1, 64 rows each
    const int warp_n = wid & 1;   // 0..1, 64 cols each

    // ldmatrix lane->address precomputation (tile-independent)
    const int rA  = warp_m * 64 + (lane & 7) + ((lane >> 3) & 1) * 8;
    const int kbA = ((lane >> 4) & 1) * 16;
    const int rB  = warp_n * 64 + (lane & 7) + ((lane >> 3) & 1) * 8;   // note: same formula as before
    const int kbB = 0;  // recomputed below to keep exact R15 mapping
    (void)kbB;

    // exact R15 lane mapping for B
    const int rB15  = warp_n * 64 + (lane & 7) + ((lane >> 4) & 1) * 8;
    const int kbB15 = ((lane >> 3) & 1) * 16;
    (void)rB;

    auto load_stage = [&](const __half* Ag, const __half* Bg, int kt, int st) {
        const int k0 = kt * BK;
        const uint32_t aT = sbase + st * STAGE_BYTES;
        const uint32_t bT = aT + 16384;
        #pragma unroll
        for (int i = 0; i < 8; i++) {
            int idx = tid + i * 128;
            int row = idx >> 3, c = idx & 7;
            cp_async16(aT + SWZ((uint32_t)(row * 128 + c * 16)),
                       (const char*)(Ag + (long)row * KPA + k0) + c * 16);
        }
        #pragma unroll
        for (int i = 0; i < 8; i++) {
            int idx = tid + i * 128;
            int row = idx >> 3, c = idx & 7;
            cp_async16(bT + SWZ((uint32_t)(row * 128 + c * 16)),
                       (const char*)(Bg + (long)row * KPB + k0) + c * 16);
        }
        CP_ASYNC_COMMIT();
    };

    int tile = blockIdx.x;
    if (tile < ntiles) {  // prologue for first tile
        const __half* Ag = A + (long)(tile / nbx) * BM * KPA;
        const __half* Bg = B + (long)(tile % nbx) * BN * KPB;
        load_stage(Ag, Bg, 0, 0);
        load_stage(Ag, Bg, 1, 1);
    }

    for (; tile < ntiles; tile += gridDim.x) {
        const int m0 = (tile / nbx) * BM;
        const int n0 = (tile % nbx) * BN;
        const __half* Ag = A + (long)m0 * KPA;
        const __half* Bg = B + (long)n0 * KPB;

        float acc[4][8][4];
        #pragma unroll
        for (int mm = 0; mm < 4; mm++)
            #pragma unroll
            for (int nt = 0; nt < 8; nt++)
                #pragma unroll
                for (int q = 0; q < 4; q++) acc[mm][nt][q] = 0.0f;

        for (int kt = 0; kt < KT; kt++) {
            if (kt + 1 < KT) { CP_ASYNC_WAIT(1); } else { CP_ASYNC_WAIT(0); }
            __syncthreads();
            if (kt + 2 < KT) load_stage(Ag, Bg, kt + 2, (kt + 2) % STAGES);

            const uint32_t aT = sbase + (kt % STAGES) * STAGE_BYTES;
            const uint32_t bT = aT + 16384;

            #pragma unroll
            for (int ks = 0; ks < 4; ks++) {
                uint32_t a[4][4];
                #pragma unroll
                for (int mm = 0; mm < 4; mm++)
                    ldsm_x4(a[mm], aT + SWZ((uint32_t)((rA + mm * 16) * 128 +
                                                       ks * 32 + kbA)));
                #pragma unroll
                for (int g = 0; g < 4; g++) {
                    uint32_t t[4];
                    ldsm_x4(t, bT + SWZ((uint32_t)((rB15 + g * 16) * 128 +
                                                   ks * 32 + kbB15)));
                    #pragma unroll
                    for (int mm = 0; mm < 4; mm++) {
                        mma16816(acc[mm][2 * g],     a[mm], t);
                        mma16816(acc[mm][2 * g + 1], a[mm], t + 2);
                    }
                }
            }
        }
        // Cross-tile prefetch: stages 0/1 were last read at kt=KT-3/KT-2,
        // strictly before the kt=KT-1 barrier -> safe to refill now.
        {
            int nxt = tile + gridDim.x;
            if (nxt < ntiles) {
                const __half* nAg = A + (long)(nxt / nbx) * BM * KPA;
                const __half* nBg = B + (long)(nxt % nbx) * BN * KPB;
                load_stage(nAg, nBg, 0, 0);
                load_stage(nAg, nBg, 1, 1);
            }
        }

        // Epilogue: fp16 half2 stores (overlaps the prefetch above)
        const int gid = lane >> 2, tig = lane & 3;
        #pragma unroll
        for (int mm = 0; mm < 4; mm++) {
            const long mrow = (long)(m0 + warp_m * 64 + mm * 16 + gid);
            __half* base0 = C + mrow * ldc + n0 + warp_n * 64 + tig * 2;
            __half* base1 = base0 + 8L * ldc;
            #pragma unroll
            for (int nt = 0; nt < 8; nt++) {
                *(__half2*)(base0 + nt * 8) =
                    __floats2half2_rn(acc[mm][nt][0], acc[mm][nt][1]);
                *(__half2*)(base1 + nt * 8) =
                    __floats2half2_rn(acc[mm][nt][2], acc[mm][nt][3]);
            }
        }
    }
}

// ============================================================================
// Fusion: one warp per token PAIR (r, r+32768), float4/half4 vectorized.
// ============================================================================
__global__ void __launch_bounds__(256) fusion_kernel(
    const float* __restrict__ x1, const float* __restrict__ x2,
    const float* __restrict__ b1, const float* __restrict__ W2,
    const float* __restrict__ b2, float* __restrict__ out) {
    const int t   = blockIdx.x * 8 + (threadIdx.x >> 5);  // pair id 0..32767
    const int lane = threadIdx.x & 31;
    const uint2*   Pr4 = (const uint2*)(g_P + (long)t * NPAD);
    const uint2*   Po4 = (const uint2*)(g_P + (long)(t + HALFM) * NPAD);
    const __half2* Pr2 = (const __half2*)(g_P + (long)t * NPAD);
    const __half2* Po2 = (const __half2*)(g_P + (long)(t + HALFM) * NPAD);
    const float4* xr4 = (const float4*)(x1 + (long)t * DIM);
    const float4* xo4 = (const float4*)(x2 + (long)t * DIM);
    const float4* c4  = (const float4*)g_c;

    float ds_r = 0.0f, dc_r = 0.0f, ds_o = 0.0f, dc_o = 0.0f;
    #pragma unroll
    for (int i = 0; i < 6; i++) {
        int d4 = lane + i * 32;                 // float4 index 0..191
        uint2 mru = Pr4[d4];
        uint2 mou = Po4[d4];
        float2 mr0 = __half22float2(*(__half2*)&mru.x);
        float2 mr1 = __half22float2(*(__half2*)&mru.y);
        float2 mo0 = __half22float2(*(__half2*)&mou.x);
        float2 mo1 = __half22float2(*(__half2*)&mou.y);
        float4 xs = xr4[d4];
        float4 xq = xo4[d4];
        float4 cc = c4[d4];
        ds_r += (mr0.x + cc.x) * xs.x + (mr0.y + cc.y) * xs.y +
                (mr1.x + cc.z) * xs.z + (mr1.y + cc.w) * xs.w;
        dc_r += mr0.x * xq.x + mr0.y * xq.y + mr1.x * xq.z + mr1.y * xq.w;
        ds_o += (mo0.x + cc.x) * xq.x + (mo0.y + cc.y) * xq.y +
                (mo1.x + cc.z) * xq.z + (mo1.y + cc.w) * xq.w;
        dc_o += mo0.x * xs.x + mo0.y * xs.y + mo1.x * xs.z + mo1.y * xs.w;
    }
    float ha_r = 0.0f, ha_o = 0.0f;
    #pragma unroll
    for (int i = 0; i < 3; i++) {
        int j2 = lane + i * 32;                 // half2 index 0..95
        float2 ar = __half22float2(Pr2[768 + j2]);   // h_a(r)
        float2 br = __half22float2(Pr2[864 + j2]);   // h_b(r)
        float2 ao = __half22float2(Po2[768 + j2]);   // h_a(o)
        float2 bo = __half22float2(Po2[864 + j2]);   // h_b(o)
        float2 bb = *(const float2*)(b1 + 2 * j2);
        float2 ww = *(const float2*)(W2 + 2 * j2);
        float r0 = ar.x + bo.x + bb.x, r1 = ar.y + bo.y + bb.y;
        float o0 = ao.x + br.x + bb.x, o1 = ao.y + br.y + bb.y;
        r0 = 0.5f * r0 * (1.0f + erff(r0 * 0.7071067811865476f));
        r1 = 0.5f * r1 * (1.0f + erff(r1 * 0.7071067811865476f));
        o0 = 0.5f * o0 * (1.0f + erff(o0 * 0.7071067811865476f));
        o1 = 0.5f * o1 * (1.0f + erff(o1 * 0.7071067811865476f));
        ha_r += r0 * ww.x + r1 * ww.y;
        ha_o += o0 * ww.x + o1 * ww.y;
    }
    #pragma unroll
    for (int o = 16; o; o >>= 1) {
        ds_r += __shfl_xor_sync(0xFFFFFFFFu, ds_r, o);
        dc_r += __shfl_xor_sync(0xFFFFFFFFu, dc_r, o);
        ds_o += __shfl_xor_sync(0xFFFFFFFFu, ds_o, o);
        dc_o += __shfl_xor_sync(0xFFFFFFFFu, dc_o, o);
        ha_r += __shfl_xor_sync(0xFFFFFFFFu, ha_r, o);
        ha_o += __shfl_xor_sync(0xFFFFFFFFu, ha_o, o);
    }
    const float bias = b2[0];
    const float SCALE = 0.03608439182435161f;  // 768^-0.5
    float rel_r = 1.0f / (1.0f + expf(-(ha_r + bias)));
    float rel_o = 1.0f / (1.0f + expf(-(ha_o + bias)));
    float d0r = ds_r * SCALE, d1r = dc_r * rel_r * SCALE;
    float d0o = ds_o * SCALE, d1o = dc_o * rel_o * SCALE;
    float mr = fmaxf(d0r, d1r), mo = fmaxf(d0o, d1o);
    float e0r = expf(d0r - mr), e1r = expf(d1r - mr);
    float e0o = expf(d0o - mo), e1o = expf(d1o - mo);
    float ir = 1.0f / (e0r + e1r), io = 1.0f / (e0o + e1o);
    float w0r = e0r * ir, w1r = e1r * ir;
    float w0o = e0o * io, w1o = e1o * io;

    float4* outr = (float4*)(out + (long)t * DIM);
    float4* outo = (float4*)(out + (long)(t + HALFM) * DIM);
    #pragma unroll
    for (int i = 0; i < 6; i++) {
        int d4 = lane + i * 32;
        uint2 vru = Pr4[192 + d4];
        uint2 vou = Po4[192 + d4];
        float4 xs = xr4[d4];     // L1/L2-warm re-read
        float4 xq = xo4[d4];
        float2 vr0 = __half22float2(*(__half2*)&vru.x);
        float2 vr1 = __half22float2(*(__half2*)&vru.y);
        float2 vo0 = __half22float2(*(__half2*)&vou.x);
        float2 vo1 = __half22float2(*(__half2*)&vou.y);
        float4 a, b;
        a.x = xs.x + w0r * vr0.x + w1r * vo0.x;
        a.y = xs.y + w0r * vr0.y + w1r * vo0.y;
        a.z = xs.z + w0r * vr1.x + w1r * vo1.x;
        a.w = xs.w + w0r * vr1.y + w1r * vo1.y;
        b.x = xq.x + w0o * vo0.x + w1o * vr0.x;
        b.y = xq.y + w0o * vo0.y + w1o * vr0.y;
        b.z = xq.z + w0o * vo1.x + w1o * vr1.x;
        b.w = xq.w + w0o * vo1.y + w1o * vr1.y;
        outr[d4] = a;
        outo[d4] = b;
    }
}

// ============================================================================
// Launch — main gemm is launch #4 (ncu profiles the 4th launch)
// ============================================================================
extern "C" void kernel_launch(void* const* d_in, const int* in_sizes, int n_in,
                              void* d_out, int out_size) {
    const float* x1    = (const float*)d_in[0];
    const float* x2    = (const float*)d_in[1];
    const float* Wq    = (const float*)d_in[2];
    const float* Wk    = (const float*)d_in[3];
    const float* Wv    = (const float*)d_in[4];
    const float* noise = (const float*)d_in[5];
    const float* W1    = (const float*)d_in[6];
    const float* b1    = (const float*)d_in[7];
    const float* W2    = (const float*)d_in[8];
    const float* b2    = (const float*)d_in[9];
    float* out = (float*)d_out;

    cudaFuncSetAttribute(hgemm_kernel,
                         cudaFuncAttributeMaxDynamicSharedMemorySize, SM_TOTAL);

    int nsm = 148;
    cudaDeviceGetAttribute(&nsm, cudaDevAttrMultiProcessorCount, 0);
    const int pgrid = 2 * nsm;   // persistent grid: 2 CTAs per SM

    __half *pXc, *pWc, *pP, *pWq16, *pWk16;
    cudaGetSymbolAddress((void**)&pXc,   g_Xc);
    cudaGetSymbolAddress((void**)&pWc,   g_Wc);
    cudaGetSymbolAddress((void**)&pP,    g_P);
    cudaGetSymbolAddress((void**)&pWq16, g_Wq16);
    cudaGetSymbolAddress((void**)&pWk16, g_Wk16);

    // 1: zero nk
    zero_nk_kernel<<<1, 768>>>();
    // 2: all fp16 conversions (qk | w-tail | x @ MLP=4)
    prep_all_kernel<<<1920 + XBLK4, 256>>>(Wq, Wk, Wv, W1,
                                           (const float4*)x1, (const float4*)x2);
    // 3: M-GEMM: g_Wc[j][i] = sum_e Wk[j,e] * Wq[i,e]  (rows 0..767), 36 tiles
    hgemm_kernel<<<36, 128, SM_TOTAL>>>(pWk16, pWq16, pWc, KPB, 36, 6);
    // 4: MAIN GEMM (profiled): P = X @ [M | Wv | W1a | W1b], 7680 tiles
    hgemm_kernel<<<pgrid, 128, SM_TOTAL>>>(pXc, pWc, pP, NPAD,
                                           (NPAD / BN) * (MTOT / BM), NPAD / BN);
    // 5,6: nk -> c (only fusion consumes them)
    nk_partial_kernel<<<dim3(6, 16), 128>>>(noise, Wk);
    c_kernel<<<96, 256>>>(Wq);
    // 7: fusion
    fusion_kernel<<<HALFM / 8, 256>>>(x1, x2, b1, W2, b2, out);
}